// round 1
// baseline (speedup 1.0000x reference)
#include <cuda_runtime.h>
#include <math.h>

#define B_  256
#define NV_ 35709
#define NR_ 107127          // NV*3
#define NF_ 70789
#define NK_ 68
#define CST 257             // coeff row stride

// output layout: [face_projection | face_color | landmarks | tri] all f32
#define OUT_COLOR ((size_t)B_ * NR_)                 // 27424512
#define OUT_LM    ((size_t)2 * B_ * NR_)             // 54849024
#define OUT_TRI   (OUT_LM + (size_t)B_ * NK_ * 3)    // 54901248

// -------- device scratch (no cudaMalloc allowed) --------
__device__ float g_mean[3];
__device__ float g_rot[B_ * 9];
__device__ float g_coeffT[224 * B_];                    // coeff transposed [j][b]
__device__ float g_face_shape[(size_t)B_ * NR_];        // ~110 MB
__device__ float g_face_norm[(size_t)B_ * NF_ * 3];     // ~217 MB
__device__ int   g_tri[NF_ * 3];
__device__ int   g_pbuf[NV_ * 8];
__device__ int   g_kp[NK_];

// ============================================================
// K_idx: detect int64-vs-int32 index dtype and convert to int32
// ============================================================
__global__ void k_idx(const void* __restrict__ tri,
                      const void* __restrict__ pbuf,
                      const void* __restrict__ kp)
{
    const int* t32 = (const int*)tri;
    bool is64 = true;
    #pragma unroll
    for (int i = 1; i < 32; i += 2) is64 = is64 && (t32[i] == 0);

    int gid = blockIdx.x * blockDim.x + threadIdx.x;
    int stride = gridDim.x * blockDim.x;
    if (is64) {
        const long long* a = (const long long*)tri;
        for (int i = gid; i < NF_ * 3; i += stride) g_tri[i] = (int)a[i];
        const long long* b = (const long long*)pbuf;
        for (int i = gid; i < NV_ * 8; i += stride) g_pbuf[i] = (int)b[i];
        const long long* c = (const long long*)kp;
        for (int i = gid; i < NK_; i += stride) g_kp[i] = (int)c[i];
    } else {
        const int* a = (const int*)tri;
        for (int i = gid; i < NF_ * 3; i += stride) g_tri[i] = a[i];
        const int* b = (const int*)pbuf;
        for (int i = gid; i < NV_ * 8; i += stride) g_pbuf[i] = b[i];
        const int* c = (const int*)kp;
        for (int i = gid; i < NK_; i += stride) g_kp[i] = c[i];
    }
}

// ============================================================
// K_prep: meanshape per-coord mean + per-batch rotation matrix
// ============================================================
__global__ void k_prep(const float* __restrict__ coeff,
                       const float* __restrict__ meanshape)
{
    __shared__ float rx[256], ry[256], rz[256];
    int t = threadIdx.x;
    float s0 = 0.f, s1 = 0.f, s2 = 0.f;
    for (int v = t; v < NV_; v += 256) {
        s0 += meanshape[v * 3 + 0];
        s1 += meanshape[v * 3 + 1];
        s2 += meanshape[v * 3 + 2];
    }
    rx[t] = s0; ry[t] = s1; rz[t] = s2;
    __syncthreads();
    for (int off = 128; off > 0; off >>= 1) {
        if (t < off) { rx[t] += rx[t + off]; ry[t] += ry[t + off]; rz[t] += rz[t + off]; }
        __syncthreads();
    }
    if (t == 0) {
        g_mean[0] = rx[0] / (float)NV_;
        g_mean[1] = ry[0] / (float)NV_;
        g_mean[2] = rz[0] / (float)NV_;
    }
    // rotation M = Rz@Ry@Rx for batch t (projection uses v @ M^T == M v)
    float ax = coeff[t * CST + 224], ay = coeff[t * CST + 225], az = coeff[t * CST + 226];
    float sx = sinf(ax), cx = cosf(ax);
    float sy = sinf(ay), cy = cosf(ay);
    float sz = sinf(az), cz = cosf(az);
    float* M = g_rot + t * 9;
    M[0] = cz * cy;  M[1] = cz * sy * sx - sz * cx;  M[2] = cz * sy * cx + sz * sx;
    M[3] = sz * cy;  M[4] = sz * sy * sx + cz * cx;  M[5] = sz * sy * cx - cz * sx;
    M[6] = -sy;      M[7] = cy * sx;                 M[8] = cy * cx;
}

// ============================================================
// K_coeffT: transpose coeff[:, 0:224] -> [j][b] for coalesced GEMM loads
// ============================================================
__global__ void k_coeffT(const float* __restrict__ coeff)
{
    int j = blockIdx.x;          // 0..223
    int b = threadIdx.x;         // 0..255
    g_coeffT[j * B_ + b] = coeff[b * CST + j];
}

// ============================================================
// K_gemm: face_shape (+mean-center) and face_texture
// block tile 64 rows x 128 batches, thread tile 4x8
// ============================================================
__device__ __forceinline__ void gemm_pass(
    const float* __restrict__ base, int kdim, int nch, int ctbase,
    int r0, int b0, int t, int rl, int bl,
    float (*sA)[64], float (*sB)[128], float acc[4][8])
{
    for (int ch = 0; ch < nch; ++ch) {
        int koff = ch * 16;
        {
            int lr = t >> 2, kq = t & 3;
            int row = r0 + lr; if (row >= NR_) row = NR_ - 1;
            const float4 v = *reinterpret_cast<const float4*>(
                base + (size_t)row * kdim + koff + kq * 4);
            sA[kq * 4 + 0][lr] = v.x;
            sA[kq * 4 + 1][lr] = v.y;
            sA[kq * 4 + 2][lr] = v.z;
            sA[kq * 4 + 3][lr] = v.w;
        }
        #pragma unroll
        for (int idx = t; idx < 16 * 128; idx += 256) {
            int k = idx >> 7, b = idx & 127;
            sB[k][b] = g_coeffT[(ctbase + koff + k) * B_ + b0 + b];
        }
        __syncthreads();
        #pragma unroll
        for (int kk = 0; kk < 16; ++kk) {
            float4 a = *reinterpret_cast<const float4*>(&sA[kk][rl]);
            float4 p = *reinterpret_cast<const float4*>(&sB[kk][bl]);
            float4 q = *reinterpret_cast<const float4*>(&sB[kk][bl + 4]);
            float av[4] = {a.x, a.y, a.z, a.w};
            float bv[8] = {p.x, p.y, p.z, p.w, q.x, q.y, q.z, q.w};
            #pragma unroll
            for (int i = 0; i < 4; i++)
                #pragma unroll
                for (int j = 0; j < 8; j++)
                    acc[i][j] = fmaf(av[i], bv[j], acc[i][j]);
        }
        __syncthreads();
    }
}

__global__ __launch_bounds__(256, 2) void k_gemm(
    const float* __restrict__ idBase, const float* __restrict__ exBase,
    const float* __restrict__ texBase, const float* __restrict__ meanshape,
    const float* __restrict__ meantex, float* __restrict__ dout)
{
    __shared__ __align__(16) float sA[16][64];
    __shared__ __align__(16) float sB[16][128];
    int t  = threadIdx.x;
    int r0 = blockIdx.x * 64;
    int b0 = blockIdx.y * 128;
    int rl = (t & 15) * 4;
    int bl = (t >> 4) * 8;

    float acc[4][8];
    #pragma unroll
    for (int i = 0; i < 4; i++)
        #pragma unroll
        for (int j = 0; j < 8; j++) acc[i][j] = 0.f;

    // ---- face_shape = idBase@id_c + exBase@ex_c ----
    gemm_pass(idBase, 80, 5, 0,   r0, b0, t, rl, bl, sA, sB, acc);
    gemm_pass(exBase, 64, 4, 80,  r0, b0, t, rl, bl, sA, sB, acc);

    #pragma unroll
    for (int i = 0; i < 4; i++) {
        int row = r0 + rl + i;
        if (row < NR_) {
            float add = meanshape[row] - g_mean[row % 3];
            #pragma unroll
            for (int j = 0; j < 8; j++)
                g_face_shape[(size_t)(b0 + bl + j) * NR_ + row] = acc[i][j] + add;
        }
    }

    // ---- face_texture -> stored in color output region (K_color reads & overwrites) ----
    #pragma unroll
    for (int i = 0; i < 4; i++)
        #pragma unroll
        for (int j = 0; j < 8; j++) acc[i][j] = 0.f;

    gemm_pass(texBase, 80, 5, 144, r0, b0, t, rl, bl, sA, sB, acc);

    #pragma unroll
    for (int i = 0; i < 4; i++) {
        int row = r0 + rl + i;
        if (row < NR_) {
            float mt = meantex[row];
            #pragma unroll
            for (int j = 0; j < 8; j++)
                dout[OUT_COLOR + (size_t)(b0 + bl + j) * NR_ + row] = acc[i][j] + mt;
        }
    }
}

// ============================================================
// K_proj: face_projection = M @ v + t
// ============================================================
__global__ void k_proj(const float* __restrict__ coeff, float* __restrict__ dout)
{
    int b = blockIdx.y, t = threadIdx.x;
    __shared__ float s[12];
    if (t < 9)        s[t] = g_rot[b * 9 + t];
    else if (t < 12)  s[t] = coeff[b * CST + 254 + (t - 9)];
    __syncthreads();
    int v = blockIdx.x * 256 + t;
    if (v >= NV_) return;
    const float* fs = g_face_shape + (size_t)b * NR_ + (size_t)v * 3;
    float x = fs[0], y = fs[1], z = fs[2];
    float* o = dout + (size_t)b * NR_ + (size_t)v * 3;
    o[0] = fmaf(s[0], x, fmaf(s[1], y, fmaf(s[2], z, s[9])));
    o[1] = fmaf(s[3], x, fmaf(s[4], y, fmaf(s[5], z, s[10])));
    o[2] = fmaf(s[6], x, fmaf(s[7], y, fmaf(s[8], z, s[11])));
}

// ============================================================
// K_face_norm: per-face cross((v1-v2),(v2-v3))
// ============================================================
__global__ void k_face_norm()
{
    int b = blockIdx.y;
    int f = blockIdx.x * 256 + threadIdx.x;
    if (f >= NF_) return;
    int i0 = g_tri[f * 3 + 0], i1 = g_tri[f * 3 + 1], i2 = g_tri[f * 3 + 2];
    const float* fs = g_face_shape + (size_t)b * NR_;
    float v1x = fs[i0 * 3], v1y = fs[i0 * 3 + 1], v1z = fs[i0 * 3 + 2];
    float v2x = fs[i1 * 3], v2y = fs[i1 * 3 + 1], v2z = fs[i1 * 3 + 2];
    float v3x = fs[i2 * 3], v3y = fs[i2 * 3 + 1], v3z = fs[i2 * 3 + 2];
    float e1x = v1x - v2x, e1y = v1y - v2y, e1z = v1z - v2z;
    float e2x = v2x - v3x, e2y = v2y - v3y, e2z = v2z - v3z;
    float* fn = g_face_norm + ((size_t)b * NF_ + f) * 3;
    fn[0] = e1y * e2z - e1z * e2y;
    fn[1] = e1z * e2x - e1x * e2z;
    fn[2] = e1x * e2y - e1y * e2x;
}

// ============================================================
// K_color: vertex normal sum + SH lighting + clip(texture*light/255)
// ============================================================
__global__ void k_color(const float* __restrict__ coeff, float* __restrict__ dout)
{
    const float A0C0   = 0.88622692545275801f;  // pi/sqrt(4pi)
    const float A1C1   = 1.77245385090551603f;  // (2pi/sqrt3)*(sqrt3/sqrt(4pi))
    const float A2C2   = 2.42703222385900050f;  // (2pi/sqrt8)*(3sqrt5/sqrt(12pi))
    const float A2C2D0 = 0.70062326950125306f;  // A2C2 * 0.5/sqrt(3)
    const float A2C2H  = 1.21351611192950025f;  // A2C2 * 0.5

    int b = blockIdx.y, t = threadIdx.x;
    __shared__ float sg[27];                    // sg[k*3+c] = g[b,k,c]
    if (t < 27) {
        int k = t / 3, c = t % 3;
        float g = coeff[b * CST + 227 + c * 9 + k];
        if (k == 0) g += 0.8f;
        sg[t] = g;
    }
    __syncthreads();
    int v = blockIdx.x * 256 + t;
    if (v >= NV_) return;

    const int* pb = g_pbuf + v * 8;
    const float* fnb = g_face_norm + (size_t)b * NF_ * 3;
    float sx = 0.f, sy = 0.f, sz = 0.f;
    #pragma unroll
    for (int i = 0; i < 8; i++) {
        int f = pb[i];
        if (f < NF_) {
            const float* fn = fnb + (size_t)f * 3;
            sx += fn[0]; sy += fn[1]; sz += fn[2];
        }
    }
    float inv = rsqrtf(sx * sx + sy * sy + sz * sz);
    float nx = sx * inv, ny = sy * inv, nz = sz * inv;

    float Y[9];
    Y[0] = A0C0;
    Y[1] = -A1C1 * ny;
    Y[2] =  A1C1 * nz;
    Y[3] = -A1C1 * nx;
    Y[4] =  A2C2 * nx * ny;
    Y[5] = -A2C2 * ny * nz;
    Y[6] =  A2C2D0 * (3.f * nz * nz - 1.f);
    Y[7] = -A2C2 * nx * nz;
    Y[8] =  A2C2H * (nx * nx - ny * ny);

    float* oc = dout + OUT_COLOR + (size_t)b * NR_ + (size_t)v * 3;
    #pragma unroll
    for (int c = 0; c < 3; c++) {
        float l = 0.f;
        #pragma unroll
        for (int k = 0; k < 9; k++) l = fmaf(Y[k], sg[k * 3 + c], l);
        float col = oc[c] * l * (1.f / 255.f);
        oc[c] = fminf(fmaxf(col, 0.f), 1.f);
    }
}

// ============================================================
// K_tail: landmarks gather + tri -> float
// ============================================================
__global__ void k_tail(float* __restrict__ dout)
{
    int i = blockIdx.x * 256 + threadIdx.x;
    const int LM_N = B_ * NK_ * 3;
    if (i < LM_N) {
        int d = i % 3, r = i / 3;
        int k = r % NK_, b = r / NK_;
        int v = g_kp[k];
        dout[OUT_LM + i] = dout[(size_t)b * NR_ + (size_t)v * 3 + d];
    } else {
        int q = i - LM_N;
        if (q < NF_ * 3) dout[OUT_TRI + q] = (float)g_tri[q];
    }
}

// ============================================================
extern "C" void kernel_launch(void* const* d_in, const int* in_sizes, int n_in,
                              void* d_out, int out_size)
{
    (void)in_sizes; (void)n_in; (void)out_size;
    const float* coeff     = (const float*)d_in[0];
    const float* meanshape = (const float*)d_in[1];
    const float* idBase    = (const float*)d_in[2];
    const float* exBase    = (const float*)d_in[3];
    const float* meantex   = (const float*)d_in[4];
    const float* texBase   = (const float*)d_in[5];
    const void*  tri       = d_in[6];
    const void*  pbuf      = d_in[7];
    const void*  kp        = d_in[8];
    float* dout = (float*)d_out;

    k_idx   <<<256, 256>>>(tri, pbuf, kp);
    k_prep  <<<1, 256>>>(coeff, meanshape);
    k_coeffT<<<224, 256>>>(coeff);
    k_gemm  <<<dim3((NR_ + 63) / 64, 2), 256>>>(idBase, exBase, texBase,
                                                meanshape, meantex, dout);
    k_proj      <<<dim3((NV_ + 255) / 256, B_), 256>>>(coeff, dout);
    k_face_norm <<<dim3((NF_ + 255) / 256, B_), 256>>>();
    k_color     <<<dim3((NV_ + 255) / 256, B_), 256>>>(coeff, dout);
    k_tail      <<<(B_ * NK_ * 3 + NF_ * 3 + 255) / 256, 256>>>(dout);
}

// round 2
// speedup vs baseline: 1.6236x; 1.6236x over previous
#include <cuda_runtime.h>
#include <math.h>

#define B_  256
#define NV_ 35709
#define NR_ 107127          // NV*3
#define NF_ 70789
#define NK_ 68
#define CST 257             // coeff row stride

// output layout: [face_projection | face_color | landmarks | tri] all f32
#define OUT_COLOR ((size_t)B_ * NR_)                 // 27424512
#define OUT_LM    ((size_t)2 * B_ * NR_)             // 54849024
#define OUT_TRI   (OUT_LM + (size_t)B_ * NK_ * 3)    // 54901248

typedef unsigned long long ull;

// -------- device scratch (no cudaMalloc allowed) --------
__device__ float g_mean[3];
__device__ float g_rot[B_ * 9];
__device__ float g_coeffT[224 * B_];                       // coeff transposed [j][b]
__device__ float g_face_shape[(size_t)NR_ * B_];           // [row][b]  ~110 MB
__device__ float g_tex[(size_t)NR_ * B_];                  // [row][b]  ~110 MB
__device__ float g_face_norm[(size_t)(NF_ + 1) * 3 * B_];  // [face*3+d][b] ~217 MB
__device__ int   g_tri[NF_ * 3];
__device__ int   g_pbuf[NV_ * 8];
__device__ int   g_kp[NK_];

// ---------- f32x2 helpers ----------
__device__ __forceinline__ ull fma2(ull a, ull b, ull c) {
    ull d;
    asm("fma.rn.f32x2 %0, %1, %2, %3;" : "=l"(d) : "l"(a), "l"(b), "l"(c));
    return d;
}
__device__ __forceinline__ ull dup2(float x) {
    ull d;
    asm("mov.b64 %0, {%1, %1};" : "=l"(d) : "f"(x));
    return d;
}
__device__ __forceinline__ void unpack2(ull v, float& lo, float& hi) {
    asm("mov.b64 {%0, %1}, %2;" : "=f"(lo), "=f"(hi) : "l"(v));
}

// ============================================================
// K_idx: detect int64-vs-int32 index dtype and convert to int32
// ============================================================
__global__ void k_idx(const void* __restrict__ tri,
                      const void* __restrict__ pbuf,
                      const void* __restrict__ kp)
{
    const int* t32 = (const int*)tri;
    bool is64 = true;
    #pragma unroll
    for (int i = 1; i < 32; i += 2) is64 = is64 && (t32[i] == 0);

    int gid = blockIdx.x * blockDim.x + threadIdx.x;
    int stride = gridDim.x * blockDim.x;
    if (is64) {
        const long long* a = (const long long*)tri;
        for (int i = gid; i < NF_ * 3; i += stride) g_tri[i] = (int)a[i];
        const long long* b = (const long long*)pbuf;
        for (int i = gid; i < NV_ * 8; i += stride) g_pbuf[i] = (int)b[i];
        const long long* c = (const long long*)kp;
        for (int i = gid; i < NK_; i += stride) g_kp[i] = (int)c[i];
    } else {
        const int* a = (const int*)tri;
        for (int i = gid; i < NF_ * 3; i += stride) g_tri[i] = a[i];
        const int* b = (const int*)pbuf;
        for (int i = gid; i < NV_ * 8; i += stride) g_pbuf[i] = b[i];
        const int* c = (const int*)kp;
        for (int i = gid; i < NK_; i += stride) g_kp[i] = c[i];
    }
}

// ============================================================
// K_prep: meanshape per-coord mean + per-batch rotation matrix
// ============================================================
__global__ void k_prep(const float* __restrict__ coeff,
                       const float* __restrict__ meanshape)
{
    __shared__ float rx[256], ry[256], rz[256];
    int t = threadIdx.x;
    float s0 = 0.f, s1 = 0.f, s2 = 0.f;
    for (int v = t; v < NV_; v += 256) {
        s0 += meanshape[v * 3 + 0];
        s1 += meanshape[v * 3 + 1];
        s2 += meanshape[v * 3 + 2];
    }
    rx[t] = s0; ry[t] = s1; rz[t] = s2;
    __syncthreads();
    for (int off = 128; off > 0; off >>= 1) {
        if (t < off) { rx[t] += rx[t + off]; ry[t] += ry[t + off]; rz[t] += rz[t + off]; }
        __syncthreads();
    }
    if (t == 0) {
        g_mean[0] = rx[0] / (float)NV_;
        g_mean[1] = ry[0] / (float)NV_;
        g_mean[2] = rz[0] / (float)NV_;
    }
    // rotation M = Rz@Ry@Rx for batch t (projection uses v @ M^T == M v)
    float ax = coeff[t * CST + 224], ay = coeff[t * CST + 225], az = coeff[t * CST + 226];
    float sx = sinf(ax), cx = cosf(ax);
    float sy = sinf(ay), cy = cosf(ay);
    float sz = sinf(az), cz = cosf(az);
    float* M = g_rot + t * 9;
    M[0] = cz * cy;  M[1] = cz * sy * sx - sz * cx;  M[2] = cz * sy * cx + sz * sx;
    M[3] = sz * cy;  M[4] = sz * sy * sx + cz * cx;  M[5] = sz * sy * cx - cz * sx;
    M[6] = -sy;      M[7] = cy * sx;                 M[8] = cy * cx;
}

// ============================================================
// K_coeffT: transpose coeff[:, 0:224] -> [j][b]
// ============================================================
__global__ void k_coeffT(const float* __restrict__ coeff)
{
    int j = blockIdx.x;
    int b = threadIdx.x;
    g_coeffT[j * B_ + b] = coeff[b * CST + j];
}

// ============================================================
// K_gemm: C[row][b] for face_shape and face_texture
// block: 64 rows x 256 batches, thread tile 4 x 16, f32x2 FMA
// ============================================================
__device__ __forceinline__ void gemm_pass(
    const float* __restrict__ base, int kdim, int nch, int ctbase,
    int r0, int t, int rl, int bl,
    float (*sA)[64], float (*sB)[256], ull acc[4][8])
{
    for (int ch = 0; ch < nch; ++ch) {
        int koff = ch * 16;
        {
            int lr = t >> 2, kq = t & 3;
            int row = r0 + lr; if (row >= NR_) row = NR_ - 1;
            const float4 v = *reinterpret_cast<const float4*>(
                base + (size_t)row * kdim + koff + kq * 4);
            sA[kq * 4 + 0][lr] = v.x;
            sA[kq * 4 + 1][lr] = v.y;
            sA[kq * 4 + 2][lr] = v.z;
            sA[kq * 4 + 3][lr] = v.w;
        }
        #pragma unroll
        for (int idx = t; idx < 16 * 256; idx += 256) {
            int k = idx >> 8, b = idx & 255;
            sB[k][b] = g_coeffT[(ctbase + koff + k) * B_ + b];
        }
        __syncthreads();
        #pragma unroll
        for (int kk = 0; kk < 16; ++kk) {
            float4 a = *reinterpret_cast<const float4*>(&sA[kk][rl]);
            ull a2[4];
            a2[0] = dup2(a.x); a2[1] = dup2(a.y); a2[2] = dup2(a.z); a2[3] = dup2(a.w);
            ulonglong2 p0 = *reinterpret_cast<const ulonglong2*>(&sB[kk][bl]);
            ulonglong2 p1 = *reinterpret_cast<const ulonglong2*>(&sB[kk][bl + 4]);
            ulonglong2 p2 = *reinterpret_cast<const ulonglong2*>(&sB[kk][bl + 8]);
            ulonglong2 p3 = *reinterpret_cast<const ulonglong2*>(&sB[kk][bl + 12]);
            ull bp[8] = {p0.x, p0.y, p1.x, p1.y, p2.x, p2.y, p3.x, p3.y};
            #pragma unroll
            for (int i = 0; i < 4; i++)
                #pragma unroll
                for (int j = 0; j < 8; j++)
                    acc[i][j] = fma2(a2[i], bp[j], acc[i][j]);
        }
        __syncthreads();
    }
}

__device__ __forceinline__ void gemm_store(
    float* __restrict__ dst, int r0, int rl, int bl,
    ull acc[4][8], const float* __restrict__ addvec, bool meancenter)
{
    #pragma unroll
    for (int i = 0; i < 4; i++) {
        int row = r0 + rl + i;
        if (row < NR_) {
            float add = addvec[row];
            if (meancenter) add -= g_mean[row - (row / 3) * 3];
            float o[16];
            #pragma unroll
            for (int j = 0; j < 8; j++) {
                float lo, hi;
                unpack2(acc[i][j], lo, hi);
                o[2 * j] = lo + add; o[2 * j + 1] = hi + add;
            }
            float* p = dst + (size_t)row * B_ + bl;
            #pragma unroll
            for (int q = 0; q < 4; q++)
                *reinterpret_cast<float4*>(p + q * 4) =
                    make_float4(o[4 * q], o[4 * q + 1], o[4 * q + 2], o[4 * q + 3]);
        }
    }
}

__global__ __launch_bounds__(256, 2) void k_gemm(
    const float* __restrict__ idBase, const float* __restrict__ exBase,
    const float* __restrict__ texBase, const float* __restrict__ meanshape,
    const float* __restrict__ meantex)
{
    __shared__ __align__(16) float sA[16][64];
    __shared__ __align__(16) float sB[16][256];
    int t  = threadIdx.x;
    int r0 = blockIdx.x * 64;
    int rl = (t & 15) * 4;
    int bl = (t >> 4) * 16;

    ull acc[4][8];
    #pragma unroll
    for (int i = 0; i < 4; i++)
        #pragma unroll
        for (int j = 0; j < 8; j++) acc[i][j] = 0ull;

    gemm_pass(idBase, 80, 5, 0,   r0, t, rl, bl, sA, sB, acc);
    gemm_pass(exBase, 64, 4, 80,  r0, t, rl, bl, sA, sB, acc);
    gemm_store(g_face_shape, r0, rl, bl, acc, meanshape, true);

    #pragma unroll
    for (int i = 0; i < 4; i++)
        #pragma unroll
        for (int j = 0; j < 8; j++) acc[i][j] = 0ull;

    gemm_pass(texBase, 80, 5, 144, r0, t, rl, bl, sA, sB, acc);
    gemm_store(g_tex, r0, rl, bl, acc, meantex, false);
}

// ============================================================
// K_proj: rotate+translate, transpose [row][b] -> dout [b][v][3]
// block: 32 vertices x 32 batches
// ============================================================
__global__ void k_proj(const float* __restrict__ coeff, float* __restrict__ dout)
{
    __shared__ float s[96][33];
    __shared__ float srot[32][12];
    int t = threadIdx.x;
    int g = blockIdx.y;
    int v0 = blockIdx.x * 32;
    int r0 = v0 * 3;

    for (int idx = t; idx < 32 * 12; idx += 256) {
        int b_l = idx / 12, k = idx % 12;
        int b = g * 32 + b_l;
        srot[b_l][k] = (k < 9) ? g_rot[b * 9 + k] : coeff[b * CST + 254 + (k - 9)];
    }
    #pragma unroll
    for (int it = 0; it < 12; it++) {
        int idx = t + it * 256;
        int row = idx >> 5, b_l = idx & 31;
        s[row][b_l] = (r0 + row < NR_) ?
            g_face_shape[(size_t)(r0 + row) * B_ + g * 32 + b_l] : 0.f;
    }
    __syncthreads();

    int b_l = t >> 3, j = t & 7;
    int b = g * 32 + b_l;
    float m0 = srot[b_l][0], m1 = srot[b_l][1], m2 = srot[b_l][2];
    float m3 = srot[b_l][3], m4 = srot[b_l][4], m5 = srot[b_l][5];
    float m6 = srot[b_l][6], m7 = srot[b_l][7], m8 = srot[b_l][8];
    float tx = srot[b_l][9], ty = srot[b_l][10], tz = srot[b_l][11];
    #pragma unroll
    for (int w = 0; w < 4; w++) {
        int v_l = j * 4 + w;
        int v = v0 + v_l;
        if (v < NV_) {
            float x = s[v_l * 3 + 0][b_l];
            float y = s[v_l * 3 + 1][b_l];
            float z = s[v_l * 3 + 2][b_l];
            float* o = dout + (size_t)b * NR_ + (size_t)v * 3;
            o[0] = fmaf(m0, x, fmaf(m1, y, fmaf(m2, z, tx)));
            o[1] = fmaf(m3, x, fmaf(m4, y, fmaf(m5, z, ty)));
            o[2] = fmaf(m6, x, fmaf(m7, y, fmaf(m8, z, tz)));
        }
    }
}

// ============================================================
// K_face_norm(g): per-face cross for 32 batches of group g
// block: 8 faces x 32 batches
// ============================================================
__global__ void k_face_norm(int g)
{
    int t = threadIdx.x;
    int fid = blockIdx.x * 8 + (t >> 5);
    int b = g * 32 + (t & 31);
    if (fid > NF_) return;
    float* fn = g_face_norm + (size_t)(fid * 3) * B_ + b;
    if (fid == NF_) {
        fn[0] = 0.f; fn[B_] = 0.f; fn[2 * B_] = 0.f;
        return;
    }
    int i0 = g_tri[fid * 3 + 0], i1 = g_tri[fid * 3 + 1], i2 = g_tri[fid * 3 + 2];
    const float* fs = g_face_shape;
    size_t o0 = (size_t)(3 * i0) * B_ + b;
    size_t o1 = (size_t)(3 * i1) * B_ + b;
    size_t o2 = (size_t)(3 * i2) * B_ + b;
    float v1x = fs[o0], v1y = fs[o0 + B_], v1z = fs[o0 + 2 * B_];
    float v2x = fs[o1], v2y = fs[o1 + B_], v2z = fs[o1 + 2 * B_];
    float v3x = fs[o2], v3y = fs[o2 + B_], v3z = fs[o2 + 2 * B_];
    float e1x = v1x - v2x, e1y = v1y - v2y, e1z = v1z - v2z;
    float e2x = v2x - v3x, e2y = v2y - v3y, e2z = v2z - v3z;
    fn[0]      = e1y * e2z - e1z * e2y;
    fn[B_]     = e1z * e2x - e1x * e2z;
    fn[2 * B_] = e1x * e2y - e1y * e2x;
}

// ============================================================
// K_color(g): vertex normal sum + SH lighting + clamp, transpose out
// block: 32 vertices x 32 batches
// ============================================================
__global__ void k_color(int g, const float* __restrict__ coeff,
                        float* __restrict__ dout)
{
    const float A0C0   = 0.88622692545275801f;
    const float A1C1   = 1.77245385090551603f;
    const float A2C2   = 2.42703222385900050f;
    const float A2C2D0 = 0.70062326950125306f;
    const float A2C2H  = 1.21351611192950025f;

    __shared__ float sc[96][33];
    __shared__ float sg[32][27];
    int t = threadIdx.x;
    int v0 = blockIdx.x * 32;

    for (int idx = t; idx < 32 * 27; idx += 256) {
        int b_l = idx / 27, kk = idx % 27;
        int k = kk / 3, c = kk % 3;
        float gv = coeff[(size_t)(g * 32 + b_l) * CST + 227 + c * 9 + k];
        if (k == 0) gv += 0.8f;
        sg[b_l][k * 3 + c] = gv;
    }
    __syncthreads();

    int vslot = t >> 5, b_l = t & 31;
    int b = g * 32 + b_l;
    #pragma unroll
    for (int it = 0; it < 4; it++) {
        int v_l = vslot + it * 8;
        int v = v0 + v_l;
        if (v < NV_) {
            const int4* pb4 = reinterpret_cast<const int4*>(g_pbuf + v * 8);
            int4 pa = pb4[0], pbv = pb4[1];
            int f[8] = {pa.x, pa.y, pa.z, pa.w, pbv.x, pbv.y, pbv.z, pbv.w};
            float sx = 0.f, sy = 0.f, sz = 0.f;
            #pragma unroll
            for (int i = 0; i < 8; i++) {
                const float* fn = g_face_norm + (size_t)(f[i] * 3) * B_ + b;
                sx += fn[0]; sy += fn[B_]; sz += fn[2 * B_];
            }
            float inv = rsqrtf(sx * sx + sy * sy + sz * sz);
            float nx = sx * inv, ny = sy * inv, nz = sz * inv;

            float Y[9];
            Y[0] = A0C0;
            Y[1] = -A1C1 * ny;
            Y[2] =  A1C1 * nz;
            Y[3] = -A1C1 * nx;
            Y[4] =  A2C2 * nx * ny;
            Y[5] = -A2C2 * ny * nz;
            Y[6] =  A2C2D0 * (3.f * nz * nz - 1.f);
            Y[7] = -A2C2 * nx * nz;
            Y[8] =  A2C2H * (nx * nx - ny * ny);

            const float* tx = g_tex + (size_t)(v * 3) * B_ + b;
            #pragma unroll
            for (int c = 0; c < 3; c++) {
                float l = 0.f;
                #pragma unroll
                for (int k = 0; k < 9; k++) l = fmaf(Y[k], sg[b_l][k * 3 + c], l);
                float col = tx[(size_t)c * B_] * l * (1.f / 255.f);
                sc[v_l * 3 + c][b_l] = fminf(fmaxf(col, 0.f), 1.f);
            }
        }
    }
    __syncthreads();

    int b_l2 = t >> 3, j = t & 7;
    int b2 = g * 32 + b_l2;
    #pragma unroll
    for (int w = 0; w < 4; w++) {
        int v_l = j * 4 + w;
        int v = v0 + v_l;
        if (v < NV_) {
            float* o = dout + OUT_COLOR + (size_t)b2 * NR_ + (size_t)v * 3;
            o[0] = sc[v_l * 3 + 0][b_l2];
            o[1] = sc[v_l * 3 + 1][b_l2];
            o[2] = sc[v_l * 3 + 2][b_l2];
        }
    }
}

// ============================================================
// K_tail: landmarks gather + tri -> float
// ============================================================
__global__ void k_tail(float* __restrict__ dout)
{
    int i = blockIdx.x * 256 + threadIdx.x;
    const int LM_N = B_ * NK_ * 3;
    if (i < LM_N) {
        int d = i % 3, r = i / 3;
        int k = r % NK_, b = r / NK_;
        int v = g_kp[k];
        dout[OUT_LM + i] = dout[(size_t)b * NR_ + (size_t)v * 3 + d];
    } else {
        int q = i - LM_N;
        if (q < NF_ * 3) dout[OUT_TRI + q] = (float)g_tri[q];
    }
}

// ============================================================
extern "C" void kernel_launch(void* const* d_in, const int* in_sizes, int n_in,
                              void* d_out, int out_size)
{
    (void)in_sizes; (void)n_in; (void)out_size;
    const float* coeff     = (const float*)d_in[0];
    const float* meanshape = (const float*)d_in[1];
    const float* idBase    = (const float*)d_in[2];
    const float* exBase    = (const float*)d_in[3];
    const float* meantex   = (const float*)d_in[4];
    const float* texBase   = (const float*)d_in[5];
    const void*  tri       = d_in[6];
    const void*  pbuf      = d_in[7];
    const void*  kp        = d_in[8];
    float* dout = (float*)d_out;

    k_idx   <<<128, 256>>>(tri, pbuf, kp);
    k_prep  <<<1, 256>>>(coeff, meanshape);
    k_coeffT<<<224, 256>>>(coeff);
    k_gemm  <<<(NR_ + 63) / 64, 256>>>(idBase, exBase, texBase, meanshape, meantex);
    k_proj  <<<dim3((NV_ + 31) / 32, 8), 256>>>(coeff, dout);
    for (int g = 0; g < 8; g++) {
        k_face_norm<<<(NF_ + 1 + 7) / 8, 256>>>(g);
        k_color    <<<(NV_ + 31) / 32, 256>>>(g, coeff, dout);
    }
    k_tail<<<(B_ * NK_ * 3 + NF_ * 3 + 255) / 256, 256>>>(dout);
}